// round 5
// baseline (speedup 1.0000x reference)
#include <cuda_runtime.h>

// WindowAttention fused kernel: one CTA per window (4096 windows).
// x(64x256) -> QKV -> S=QK^T + phi/theta bias -> softmax -> P@V -> proj -> out
// All fp32 math via packed fma.rn.f32x2 (bit-identical to scalar fp32 FFMA).

#define NTOK 64
#define DIMC 256
#define XP   260   // padded row stride for Xs / A (Q,V)
#define KTP  64    // Kt row stride (Kt[d][j])
#define SSP  65    // P row stride
#define WTP  256   // W tile row stride

// smem layout (floats)
#define OFF_XS  0
#define OFF_A   16640      // 64*260
#define OFF_BT  33280      // + 64*260
#define OFF_SS  49664      // + 256*64
#define OFF_WT  53824      // + 64*65
#define OFF_TAB 57920      // + 16*256
#define SMEM_FLOATS 57984
#define SMEM_BYTES (SMEM_FLOATS * 4)

__device__ __forceinline__ unsigned long long pack2(float lo, float hi) {
    unsigned long long r;
    asm("mov.b64 %0, {%1, %2};" : "=l"(r) : "f"(lo), "f"(hi));
    return r;
}
__device__ __forceinline__ float2 unpack2(unsigned long long v) {
    float2 f;
    asm("mov.b64 {%0, %1}, %2;" : "=f"(f.x), "=f"(f.y) : "l"(v));
    return f;
}
__device__ __forceinline__ void ffma2(unsigned long long& d,
                                      unsigned long long a,
                                      unsigned long long b) {
    asm("fma.rn.f32x2 %0, %1, %2, %0;" : "+l"(d) : "l"(a), "l"(b));
}

// C(64x256) = Xin(64x256, row stride ldX) @ Wg(256x256 slice, row stride ldW)
// acc[rr][q*2+p] packs output cols (ct*4 + q*64 + 2p, +1) for row rt*4+rr.
__device__ __forceinline__ void gemm64x256(
    const float* __restrict__ Xin, int ldX,
    const float* __restrict__ Wg, int ldW,
    float* __restrict__ Wt, int tid,
    unsigned long long acc[4][8])
{
    const int ct = tid & 15;
    const int rt = tid >> 4;
#pragma unroll
    for (int rr = 0; rr < 4; ++rr)
#pragma unroll
        for (int qq = 0; qq < 8; ++qq) acc[rr][qq] = 0ull;

    for (int k0 = 0; k0 < 256; k0 += 16) {
        __syncthreads();
        // cooperative load of W tile [16][256]
#pragma unroll
        for (int i = 0; i < 4; ++i) {
            int e  = tid + 256 * i;        // float4 index, 0..1023
            int kk = e >> 6;
            int c4 = e & 63;
            *(float4*)&Wt[kk * WTP + c4 * 4] =
                *(const float4*)&Wg[(size_t)(k0 + kk) * ldW + c4 * 4];
        }
        __syncthreads();
#pragma unroll
        for (int kk = 0; kk < 16; ++kk) {
            unsigned long long xp[4];
#pragma unroll
            for (int rr = 0; rr < 4; ++rr) {
                float xv = Xin[(rt * 4 + rr) * ldX + k0 + kk];
                xp[rr] = pack2(xv, xv);
            }
#pragma unroll
            for (int q = 0; q < 4; ++q) {
                ulonglong2 wv = *(const ulonglong2*)&Wt[kk * WTP + ct * 4 + q * 64];
#pragma unroll
                for (int rr = 0; rr < 4; ++rr) {
                    ffma2(acc[rr][q * 2 + 0], xp[rr], wv.x);
                    ffma2(acc[rr][q * 2 + 1], xp[rr], wv.y);
                }
            }
        }
    }
}

__global__ void __launch_bounds__(256, 1)
win_attn_kernel(const float* __restrict__ x,
                const float* __restrict__ theta_max,
                const float* __restrict__ qkv_w,
                const float* __restrict__ qkv_b,
                const float* __restrict__ proj_w,
                const float* __restrict__ proj_b,
                const float* __restrict__ a_p,
                const float* __restrict__ b_p,
                const float* __restrict__ a_r,
                const float* __restrict__ b_r,
                float* __restrict__ out)
{
    extern __shared__ float sm[];
    float* Xs  = sm + OFF_XS;
    float* A   = sm + OFF_A;    // Q, then V
    float* Bt  = sm + OFF_BT;   // Kt[256][64], then O[64][256]
    float* Ss  = sm + OFF_SS;   // P[64][65]
    float* Wt  = sm + OFF_WT;
    float* tab = sm + OFF_TAB;  // a_p, b_p, a_r, b_r (16 floats apart)

    const int tid = threadIdx.x;
    const int w   = blockIdx.x;
    const float tm = __ldg(&theta_max[w >> 6]);

    if (tid < 15) {
        tab[tid]      = a_p[tid];
        tab[16 + tid] = b_p[tid];
        tab[32 + tid] = a_r[tid];
        tab[48 + tid] = b_r[tid];
    }

    // load x window into Xs (padded rows)
    const float4* xg = (const float4*)(x + (size_t)w * NTOK * DIMC);
#pragma unroll
    for (int i = 0; i < 16; ++i) {
        int e   = tid + 256 * i;   // 0..4095 float4s
        int row = e >> 6;
        int c4  = e & 63;
        *(float4*)&Xs[row * XP + c4 * 4] = xg[e];
    }

    const int ct = tid & 15;
    const int rt = tid >> 4;
    unsigned long long acc[4][8];

    // ---- Q = (Xs @ Wq + bq) * scale -> A ----
    gemm64x256(Xs, XP, qkv_w + 0, 768, Wt, tid, acc);
#pragma unroll
    for (int rr = 0; rr < 4; ++rr)
#pragma unroll
        for (int q = 0; q < 4; ++q)
#pragma unroll
            for (int p = 0; p < 2; ++p) {
                int c = ct * 4 + q * 64 + p * 2;
                int r = rt * 4 + rr;
                float2 v = unpack2(acc[rr][q * 2 + p]);
                v.x = (v.x + qkv_b[c])     * 0.0625f;
                v.y = (v.y + qkv_b[c + 1]) * 0.0625f;
                *(float2*)&A[r * XP + c] = v;
            }

    // ---- K = Xs @ Wk + bk -> Bt transposed: Bt[c][r] ----
    gemm64x256(Xs, XP, qkv_w + 256, 768, Wt, tid, acc);
#pragma unroll
    for (int rr = 0; rr < 4; ++rr)
#pragma unroll
        for (int q = 0; q < 4; ++q)
#pragma unroll
            for (int p = 0; p < 2; ++p) {
                int c = ct * 4 + q * 64 + p * 2;
                int r = rt * 4 + rr;
                float2 v = unpack2(acc[rr][q * 2 + p]);
                Bt[(c)     * KTP + r] = v.x + qkv_b[256 + c];
                Bt[(c + 1) * KTP + r] = v.y + qkv_b[256 + c + 1];
            }
    __syncthreads();

    // ---- S = Q @ K^T, add biases, softmax -> Ss ----
    {
        const int i  = tid >> 2;
        const int j0 = (tid & 3) * 16;
        unsigned long long sp[8];
#pragma unroll
        for (int p = 0; p < 8; ++p) sp[p] = 0ull;
        for (int d = 0; d < 256; ++d) {
            float qv = A[i * XP + d];
            unsigned long long qp = pack2(qv, qv);
#pragma unroll
            for (int e4 = 0; e4 < 4; ++e4) {
                ulonglong2 kv = *(const ulonglong2*)&Bt[d * KTP + j0 + e4 * 4];
                ffma2(sp[e4 * 2 + 0], qp, kv.x);
                ffma2(sp[e4 * 2 + 1], qp, kv.y);
            }
        }
        float s[16];
#pragma unroll
        for (int p = 0; p < 8; ++p) {
            float2 v = unpack2(sp[p]);
            s[2 * p] = v.x; s[2 * p + 1] = v.y;
        }
        const float C_AZ = 6.283185307179586f / 64.0f;   // 2*pi/W_RES
        const float tms  = tm * 0.015625f;               // tm / H_RES
        float mx = -1e30f;
#pragma unroll
        for (int jj = 0; jj < 16; ++jj) {
            int j  = j0 + jj;
            int dy = (i >> 3) - (j >> 3);   // radius
            int dx = (i & 7)  - (j & 7);    // azimuth
            int ai = (dx < 0) ? dx + 15 : dx;
            int ri = (dy < 0) ? dy + 15 : dy;
            float sph, cph, srn, crn;
            sincosf((float)dx * C_AZ, &sph, &cph);
            sincosf((float)dy * tms,  &srn, &crn);
            float bias = tab[ai] * cph + tab[16 + ai] * sph
                       + tab[32 + ri] * crn + tab[48 + ri] * srn;
            s[jj] += bias;
            mx = fmaxf(mx, s[jj]);
        }
        mx = fmaxf(mx, __shfl_xor_sync(0xffffffffu, mx, 1));
        mx = fmaxf(mx, __shfl_xor_sync(0xffffffffu, mx, 2));
        float sum = 0.0f;
#pragma unroll
        for (int jj = 0; jj < 16; ++jj) {
            s[jj] = expf(s[jj] - mx);
            sum += s[jj];
        }
        sum += __shfl_xor_sync(0xffffffffu, sum, 1);
        sum += __shfl_xor_sync(0xffffffffu, sum, 2);
        float inv = 1.0f / sum;
#pragma unroll
        for (int jj = 0; jj < 16; ++jj)
            Ss[i * SSP + j0 + jj] = s[jj] * inv;
    }
    // gemm's leading __syncthreads() orders Ss/Q reads before A (V) overwrite

    // ---- V = Xs @ Wv + bv -> A ----
    gemm64x256(Xs, XP, qkv_w + 512, 768, Wt, tid, acc);
#pragma unroll
    for (int rr = 0; rr < 4; ++rr)
#pragma unroll
        for (int q = 0; q < 4; ++q)
#pragma unroll
            for (int p = 0; p < 2; ++p) {
                int c = ct * 4 + q * 64 + p * 2;
                int r = rt * 4 + rr;
                float2 v = unpack2(acc[rr][q * 2 + p]);
                v.x += qkv_b[512 + c];
                v.y += qkv_b[512 + c + 1];
                *(float2*)&A[r * XP + c] = v;
            }
    __syncthreads();

    // ---- O = P @ V -> Bt[64][256] ----
    {
#pragma unroll
        for (int rr = 0; rr < 4; ++rr)
#pragma unroll
            for (int qq = 0; qq < 8; ++qq) acc[rr][qq] = 0ull;
#pragma unroll 8
        for (int j = 0; j < 64; ++j) {
            unsigned long long pp[4];
#pragma unroll
            for (int rr = 0; rr < 4; ++rr) {
                float pv = Ss[(rt * 4 + rr) * SSP + j];
                pp[rr] = pack2(pv, pv);
            }
#pragma unroll
            for (int q = 0; q < 4; ++q) {
                ulonglong2 vv = *(const ulonglong2*)&A[j * XP + ct * 4 + q * 64];
#pragma unroll
                for (int rr = 0; rr < 4; ++rr) {
                    ffma2(acc[rr][q * 2 + 0], pp[rr], vv.x);
                    ffma2(acc[rr][q * 2 + 1], pp[rr], vv.y);
                }
            }
        }
#pragma unroll
        for (int rr = 0; rr < 4; ++rr)
#pragma unroll
            for (int q = 0; q < 4; ++q)
#pragma unroll
                for (int p = 0; p < 2; ++p) {
                    int c = ct * 4 + q * 64 + p * 2;
                    int r = rt * 4 + rr;
                    *(float2*)&Bt[r * 256 + c] = unpack2(acc[rr][q * 2 + p]);
                }
    }
    // proj gemm's leading sync orders O writes before reads

    // ---- out = O @ proj_w + proj_b ----
    gemm64x256(Bt, 256, proj_w, 256, Wt, tid, acc);
    float* og = out + (size_t)w * NTOK * DIMC;
#pragma unroll
    for (int rr = 0; rr < 4; ++rr)
#pragma unroll
        for (int q = 0; q < 4; ++q)
#pragma unroll
            for (int p = 0; p < 2; ++p) {
                int c = ct * 4 + q * 64 + p * 2;
                int r = rt * 4 + rr;
                float2 v = unpack2(acc[rr][q * 2 + p]);
                v.x += proj_b[c];
                v.y += proj_b[c + 1];
                *(float2*)&og[r * 256 + c] = v;
            }
}

extern "C" void kernel_launch(void* const* d_in, const int* in_sizes, int n_in,
                              void* d_out, int out_size)
{
    (void)in_sizes; (void)n_in; (void)out_size;
    const float* x         = (const float*)d_in[0];
    const float* theta_max = (const float*)d_in[1];
    const float* qkv_w     = (const float*)d_in[2];
    const float* qkv_b     = (const float*)d_in[3];
    const float* proj_w    = (const float*)d_in[4];
    const float* proj_b    = (const float*)d_in[5];
    const float* a_p       = (const float*)d_in[6];
    const float* b_p       = (const float*)d_in[7];
    const float* a_r       = (const float*)d_in[8];
    const float* b_r       = (const float*)d_in[9];
    float* out = (float*)d_out;

    cudaFuncSetAttribute(win_attn_kernel,
                         cudaFuncAttributeMaxDynamicSharedMemorySize, SMEM_BYTES);
    win_attn_kernel<<<4096, 256, SMEM_BYTES>>>(
        x, theta_max, qkv_w, qkv_b, proj_w, proj_b,
        a_p, b_p, a_r, b_r, out);
}

// round 7
// speedup vs baseline: 1.3987x; 1.3987x over previous
#include <cuda_runtime.h>
#include <cuda_bf16.h>
#include <cstdint>

// ===================== scratch (static device arrays; no allocs) ============
__device__ float          g_qkv[262144ull * 768];          // 768 MB fp32 QKV
__device__ __nv_bfloat16  g_xhi[262144ull * 256];          // X split hi/lo
__device__ __nv_bfloat16  g_xlo[262144ull * 256];
__device__ __nv_bfloat16  g_ohi[262144ull * 256];          // O split hi/lo
__device__ __nv_bfloat16  g_olo[262144ull * 256];
__device__ __nv_bfloat16  g_wqkv_hi[768 * 256];            // W^T [n][k]
__device__ __nv_bfloat16  g_wqkv_lo[768 * 256];
__device__ __nv_bfloat16  g_wproj_hi[256 * 256];
__device__ __nv_bfloat16  g_wproj_lo[256 * 256];

// ===================== helpers ==============================================
__device__ __forceinline__ uint32_t smem_to_u32(const void* p) {
    uint32_t a;
    asm("{ .reg .u64 t; cvta.to.shared.u64 t, %1; cvt.u32.u64 %0, t; }"
        : "=r"(a) : "l"(p));
    return a;
}
__device__ __forceinline__ void ldsm4(uint32_t (&r)[4], uint32_t addr) {
    asm volatile("ldmatrix.sync.aligned.m8n8.x4.shared.b16 {%0,%1,%2,%3}, [%4];"
                 : "=r"(r[0]), "=r"(r[1]), "=r"(r[2]), "=r"(r[3]) : "r"(addr));
}
__device__ __forceinline__ void mma16816(float (&d)[4], const uint32_t (&a)[4],
                                         uint32_t b0, uint32_t b1) {
    asm volatile("mma.sync.aligned.m16n8k16.row.col.f32.bf16.bf16.f32 "
                 "{%0,%1,%2,%3}, {%4,%5,%6,%7}, {%8,%9}, {%0,%1,%2,%3};"
                 : "+f"(d[0]), "+f"(d[1]), "+f"(d[2]), "+f"(d[3])
                 : "r"(a[0]), "r"(a[1]), "r"(a[2]), "r"(a[3]), "r"(b0), "r"(b1));
}
// f32x2 helpers (scalar attention math)
__device__ __forceinline__ unsigned long long pack2(float lo, float hi) {
    unsigned long long r;
    asm("mov.b64 %0, {%1, %2};" : "=l"(r) : "f"(lo), "f"(hi));
    return r;
}
__device__ __forceinline__ float2 unpack2(unsigned long long v) {
    float2 f;
    asm("mov.b64 {%0, %1}, %2;" : "=f"(f.x), "=f"(f.y) : "l"(v));
    return f;
}
__device__ __forceinline__ void ffma2(unsigned long long& d,
                                      unsigned long long a, unsigned long long b) {
    asm("fma.rn.f32x2 %0, %1, %2, %0;" : "+l"(d) : "l"(a), "l"(b));
}

// ===================== prep kernels =========================================
__global__ void __launch_bounds__(1024) split_x_kernel(const float* __restrict__ x) {
    size_t idx = (size_t)blockIdx.x * 1024 + threadIdx.x;  // float4 index
    float4 v = ((const float4*)x)[idx];
    __nv_bfloat162 h0, h1, l0, l1;
    h0.x = __float2bfloat16(v.x); h0.y = __float2bfloat16(v.y);
    h1.x = __float2bfloat16(v.z); h1.y = __float2bfloat16(v.w);
    l0.x = __float2bfloat16(v.x - __bfloat162float(h0.x));
    l0.y = __float2bfloat16(v.y - __bfloat162float(h0.y));
    l1.x = __float2bfloat16(v.z - __bfloat162float(h1.x));
    l1.y = __float2bfloat16(v.w - __bfloat162float(h1.y));
    ((__nv_bfloat162*)g_xhi)[idx * 2]     = h0;
    ((__nv_bfloat162*)g_xhi)[idx * 2 + 1] = h1;
    ((__nv_bfloat162*)g_xlo)[idx * 2]     = l0;
    ((__nv_bfloat162*)g_xlo)[idx * 2 + 1] = l1;
}

__global__ void __launch_bounds__(512) split_w_kernel(const float* __restrict__ qkv_w,
                                                      const float* __restrict__ proj_w) {
    int idx = blockIdx.x * 512 + threadIdx.x;
    float v; __nv_bfloat16 *ph, *pl; int off;
    if (idx < 196608) {
        int n = idx >> 8, k = idx & 255;
        v = qkv_w[k * 768 + n];
        ph = g_wqkv_hi; pl = g_wqkv_lo; off = n * 256 + k;
    } else {
        int j = idx - 196608;
        int n = j >> 8, k = j & 255;
        v = proj_w[k * 256 + n];
        ph = g_wproj_hi; pl = g_wproj_lo; off = n * 256 + k;
    }
    __nv_bfloat16 h = __float2bfloat16(v);
    ph[off] = h;
    pl[off] = __float2bfloat16(v - __bfloat162float(h));
}

// ===================== split-bf16 HMMA GEMM =================================
// C[128 x 128] tile = A[128 x 256] @ W^T, 3-term bf16 split, fp32 accum.
// MODE 0: A=X hi/lo, W=qkv_w, C=g_qkv (ld 768).  MODE 1: A=O, W=proj, C=out.
// smem tiles: 128 rows x 32 k bf16, row stride 40 bf16 (80 B) -> ldmatrix
// conflict-free (i*80 mod 128 hits all eight 16B slots).
#define T_AH 0
#define T_AL 10240
#define T_BH 20480
#define T_BL 30720

template<int MODE>
__global__ void __launch_bounds__(256, 2)
gemm_mma_kernel(const float* __restrict__ bias, float* __restrict__ Cext)
{
    __shared__ __align__(16) unsigned char sm[40960];
    const __nv_bfloat16* Ahi = (MODE == 0) ? g_xhi : g_ohi;
    const __nv_bfloat16* Alo = (MODE == 0) ? g_xlo : g_olo;
    const __nv_bfloat16* Whi = (MODE == 0) ? g_wqkv_hi : g_wproj_hi;
    const __nv_bfloat16* Wlo = (MODE == 0) ? g_wqkv_lo : g_wproj_lo;
    const int ldC = (MODE == 0) ? 768 : 256;
    float* C = (MODE == 0) ? g_qkv : Cext;

    const int tid  = threadIdx.x;
    const int lane = tid & 31;
    const int wid  = tid >> 5;
    const int m0   = blockIdx.x * 128;
    const int n0   = blockIdx.y * 128;
    const int wm   = (wid & 3) * 32;
    const int wn   = (wid >> 2) * 64;
    const uint32_t sb = smem_to_u32(sm);

    float acc[2][8][4];
#pragma unroll
    for (int a = 0; a < 2; ++a)
#pragma unroll
        for (int b = 0; b < 8; ++b)
#pragma unroll
            for (int c = 0; c < 4; ++c) acc[a][b][c] = 0.0f;

    const int arow = (lane & 7) + ((lane >> 3) & 1) * 8;   // ldmatrix row pattern
    const int kqof = (lane >> 4) * 8;                      // ldmatrix k pattern

    for (int kc = 0; kc < 8; ++kc) {
        const int kb = kc * 32;
#pragma unroll
        for (int it = 0; it < 2; ++it) {
            int e   = tid + it * 256;      // 0..511 int4 slots
            int row = e >> 2;
            int kq  = e & 3;
            size_t goffA = (size_t)(m0 + row) * 256 + kb + kq * 8;
            size_t goffB = (size_t)(n0 + row) * 256 + kb + kq * 8;
            uint32_t soff = (uint32_t)(row * 80 + kq * 16);
            *(int4*)(sm + T_AH + soff) = *(const int4*)(Ahi + goffA);
            *(int4*)(sm + T_AL + soff) = *(const int4*)(Alo + goffA);
            *(int4*)(sm + T_BH + soff) = *(const int4*)(Whi + goffB);
            *(int4*)(sm + T_BL + soff) = *(const int4*)(Wlo + goffB);
        }
        __syncthreads();
#pragma unroll
        for (int ks = 0; ks < 2; ++ks) {
            const int kcol = ks * 16 + kqof;
            uint32_t ah[2][4], al[2][4];
#pragma unroll
            for (int mf = 0; mf < 2; ++mf) {
                uint32_t ad = sb + (uint32_t)((wm + mf * 16 + arow) * 80 + kcol * 2);
                ldsm4(ah[mf], ad + T_AH);
                ldsm4(al[mf], ad + T_AL);
            }
#pragma unroll
            for (int np = 0; np < 4; ++np) {
                uint32_t bd = sb + (uint32_t)((wn + np * 16 + arow) * 80 + kcol * 2);
                uint32_t bh[4], bl[4];
                ldsm4(bh, bd + T_BH);
                ldsm4(bl, bd + T_BL);
#pragma unroll
                for (int mf = 0; mf < 2; ++mf)
#pragma unroll
                    for (int nf = 0; nf < 2; ++nf) {
                        float (&d)[4] = acc[mf][np * 2 + nf];
                        mma16816(d, ah[mf], bh[nf], bh[nf + 2]);
                        mma16816(d, ah[mf], bl[nf], bl[nf + 2]);
                        mma16816(d, al[mf], bh[nf], bh[nf + 2]);
                    }
            }
        }
        __syncthreads();
    }

    // epilogue: d0/d1 -> (row g, col 2tg..+1); d2/d3 -> row g+8
    const int g   = lane >> 2;
    const int tg2 = (lane & 3) * 2;
#pragma unroll
    for (int mf = 0; mf < 2; ++mf) {
        const int row = m0 + wm + mf * 16 + g;
#pragma unroll
        for (int nfi = 0; nfi < 8; ++nfi) {
            const int col = n0 + wn + nfi * 8 + tg2;
            float bx = __ldg(&bias[col]);
            float by = __ldg(&bias[col + 1]);
            *(float2*)&C[(size_t)row * ldC + col] =
                make_float2(acc[mf][nfi][0] + bx, acc[mf][nfi][1] + by);
            *(float2*)&C[(size_t)(row + 8) * ldC + col] =
                make_float2(acc[mf][nfi][2] + bx, acc[mf][nfi][3] + by);
        }
    }
}

// ===================== attention (scalar f32x2, 512 threads) =================
// smem floats: Q[64][260] @0, V[64][260] @16640, Kt[256][68] @33280,
//              P[64][65] @50688, tab[64] @54848 -> 54912 floats = 219648 B
#define A_OFF_Q  0
#define A_OFF_V  16640
#define A_OFF_KT 33280
#define A_OFF_P  50688
#define A_OFF_T  54848
#define ATTN_SMEM (54912 * 4)

__global__ void __launch_bounds__(512, 1)
attn_kernel(const float* __restrict__ theta_max,
            const float* __restrict__ a_p, const float* __restrict__ b_p,
            const float* __restrict__ a_r, const float* __restrict__ b_r)
{
    extern __shared__ float sf[];
    float* Qs  = sf + A_OFF_Q;
    float* Vs  = sf + A_OFF_V;
    float* Kt  = sf + A_OFF_KT;
    float* Ps  = sf + A_OFF_P;
    float* tab = sf + A_OFF_T;

    const int tid = threadIdx.x;
    const int w   = blockIdx.x;
    const float tm = __ldg(&theta_max[w >> 6]);
    if (tid < 15) {
        tab[tid]      = a_p[tid];
        tab[16 + tid] = b_p[tid];
        tab[32 + tid] = a_r[tid];
        tab[48 + tid] = b_r[tid];
    }

    const float* qg = g_qkv + (size_t)w * 64 * 768;
#pragma unroll
    for (int it = 0; it < 8; ++it) {
        int t = tid + it * 512;            // 0..4095
        int row = t >> 6, c4 = t & 63;
        *(float4*)&Qs[row * 260 + c4 * 4] = *(const float4*)&qg[row * 768 + c4 * 4];
        *(float4*)&Vs[row * 260 + c4 * 4] = *(const float4*)&qg[row * 768 + 512 + c4 * 4];
    }
#pragma unroll
    for (int it = 0; it < 32; ++it) {
        int e = tid + it * 512;            // 0..16383
        int d = e & 255, i = e >> 8;
        Kt[d * 68 + i] = qg[i * 768 + 256 + d];
    }
    __syncthreads();

    // ---- S = scale*(Q K^T) + bias, softmax -> Ps ----
    {
        const int i  = tid >> 3;
        const int j0 = (tid & 7) * 8;
        unsigned long long sp[4] = {0ull, 0ull, 0ull, 0ull};
        for (int d = 0; d < 256; ++d) {
            float qv = Qs[i * 260 + d];
            unsigned long long qp = pack2(qv, qv);
            ulonglong2 k0 = *(const ulonglong2*)&Kt[d * 68 + j0];
            ulonglong2 k1 = *(const ulonglong2*)&Kt[d * 68 + j0 + 4];
            ffma2(sp[0], qp, k0.x); ffma2(sp[1], qp, k0.y);
            ffma2(sp[2], qp, k1.x); ffma2(sp[3], qp, k1.y);
        }
        float s[8];
#pragma unroll
        for (int p = 0; p < 4; ++p) {
            float2 v = unpack2(sp[p]);
            s[2 * p] = v.x; s[2 * p + 1] = v.y;
        }
        const float C_AZ = 6.283185307179586f / 64.0f;
        const float tms  = tm * 0.015625f;
        float mx = -1e30f;
#pragma unroll
        for (int jj = 0; jj < 8; ++jj) {
            int j  = j0 + jj;
            int dy = (i >> 3) - (j >> 3);
            int dx = (i & 7)  - (j & 7);
            int ai = (dx < 0) ? dx + 15 : dx;
            int ri = (dy < 0) ? dy + 15 : dy;
            float sph, cph, srn, crn;
            sincosf((float)dx * C_AZ, &sph, &cph);
            sincosf((float)dy * tms,  &srn, &crn);
            float bias = tab[ai] * cph + tab[16 + ai] * sph
                       + tab[32 + ri] * crn + tab[48 + ri] * srn;
            s[jj] = s[jj] * 0.0625f + bias;
            mx = fmaxf(mx, s[jj]);
        }
        mx = fmaxf(mx, __shfl_xor_sync(0xffffffffu, mx, 1));
        mx = fmaxf(mx, __shfl_xor_sync(0xffffffffu, mx, 2));
        mx = fmaxf(mx, __shfl_xor_sync(0xffffffffu, mx, 4));
        float sum = 0.0f;
#pragma unroll
        for (int jj = 0; jj < 8; ++jj) {
            s[jj] = expf(s[jj] - mx);
            sum += s[jj];
        }
        sum += __shfl_xor_sync(0xffffffffu, sum, 1);
        sum += __shfl_xor_sync(0xffffffffu, sum, 2);
        sum += __shfl_xor_sync(0xffffffffu, sum, 4);
        float inv = 1.0f / sum;
#pragma unroll
        for (int jj = 0; jj < 8; ++jj)
            Ps[i * 65 + j0 + jj] = s[jj] * inv;
    }
    __syncthreads();

    // ---- O = P @ V -> g_ohi/g_olo (bf16 split) ----
    {
        const int ct = tid & 15;
        const int rt = tid >> 4;           // 0..31, 2 rows each
        unsigned long long acc[2][8];
#pragma unroll
        for (int rr = 0; rr < 2; ++rr)
#pragma unroll
            for (int q = 0; q < 8; ++q) acc[rr][q] = 0ull;
#pragma unroll 8
        for (int j = 0; j < 64; ++j) {
            float p0 = Ps[(rt * 2)     * 65 + j];
            float p1 = Ps[(rt * 2 + 1) * 65 + j];
            unsigned long long pp0 = pack2(p0, p0);
            unsigned long long pp1 = pack2(p1, p1);
#pragma unroll
            for (int q = 0; q < 4; ++q) {
                ulonglong2 vv = *(const ulonglong2*)&Vs[j * 260 + ct * 4 + q * 64];
                ffma2(acc[0][q * 2 + 0], pp0, vv.x);
                ffma2(acc[0][q * 2 + 1], pp0, vv.y);
                ffma2(acc[1][q * 2 + 0], pp1, vv.x);
                ffma2(acc[1][q * 2 + 1], pp1, vv.y);
            }
        }
#pragma unroll
        for (int rr = 0; rr < 2; ++rr) {
            size_t r = (size_t)w * 64 + rt * 2 + rr;
#pragma unroll
            for (int q = 0; q < 4; ++q)
#pragma unroll
                for (int p = 0; p < 2; ++p) {
                    int c = ct * 4 + q * 64 + p * 2;
                    float2 v = unpack2(acc[rr][q * 2 + p]);
                    __nv_bfloat162 hv, lv;
                    hv.x = __float2bfloat16(v.x);
                    hv.y = __float2bfloat16(v.y);
                    lv.x = __float2bfloat16(v.x - __bfloat162float(hv.x));
                    lv.y = __float2bfloat16(v.y - __bfloat162float(hv.y));
                    *(__nv_bfloat162*)&g_ohi[r * 256 + c] = hv;
                    *(__nv_bfloat162*)&g_olo[r * 256 + c] = lv;
                }
        }
    }
}

// ===================== launch ================================================
extern "C" void kernel_launch(void* const* d_in, const int* in_sizes, int n_in,
                              void* d_out, int out_size)
{
    (void)in_sizes; (void)n_in; (void)out_size;
    const float* x         = (const float*)d_in[0];
    const float* theta_max = (const float*)d_in[1];
    const float* qkv_w     = (const float*)d_in[2];
    const float* qkv_b     = (const float*)d_in[3];
    const float* proj_w    = (const float*)d_in[4];
    const float* proj_b    = (const float*)d_in[5];
    const float* a_p       = (const float*)d_in[6];
    const float* b_p       = (const float*)d_in[7];
    const float* a_r       = (const float*)d_in[8];
    const float* b_r       = (const float*)d_in[9];
    float* out = (float*)d_out;

    cudaFuncSetAttribute(attn_kernel,
                         cudaFuncAttributeMaxDynamicSharedMemorySize, ATTN_SMEM);

    split_x_kernel<<<16384, 1024>>>(x);                       // 16.7M float4
    split_w_kernel<<<512, 512>>>(qkv_w, proj_w);              // 262144 elems
    gemm_mma_kernel<0><<<dim3(2048, 6), 256>>>(qkv_b, nullptr);
    attn_kernel<<<4096, 512, ATTN_SMEM>>>(theta_max, a_p, b_p, a_r, b_r);
    gemm_mma_kernel<1><<<dim3(2048, 2), 256>>>(proj_b, out);
}

// round 8
// speedup vs baseline: 2.0756x; 1.4840x over previous
#include <cuda_runtime.h>
#include <cuda_bf16.h>
#include <cstdint>

// ===================== scratch (static device arrays; no allocs) ============
__device__ __nv_bfloat16  g_xhi[262144ull * 256];          // X split hi/lo
__device__ __nv_bfloat16  g_xlo[262144ull * 256];
__device__ __nv_bfloat16  g_qh[262144ull * 256];           // Q (scaled+bias) hi/lo
__device__ __nv_bfloat16  g_ql[262144ull * 256];
__device__ __nv_bfloat16  g_kh[262144ull * 256];           // K hi/lo
__device__ __nv_bfloat16  g_kl[262144ull * 256];
__device__ __nv_bfloat16  g_vth[4096ull * 256 * 64];       // V^T per window [d][j]
__device__ __nv_bfloat16  g_vtl[4096ull * 256 * 64];
__device__ __nv_bfloat16  g_ohi[262144ull * 256];          // attn out hi/lo
__device__ __nv_bfloat16  g_olo[262144ull * 256];
__device__ __nv_bfloat16  g_wqkv_hi[768 * 256];            // W^T [n][k]
__device__ __nv_bfloat16  g_wqkv_lo[768 * 256];
__device__ __nv_bfloat16  g_wproj_hi[256 * 256];
__device__ __nv_bfloat16  g_wproj_lo[256 * 256];

// ===================== helpers ==============================================
__device__ __forceinline__ uint32_t smem_to_u32(const void* p) {
    uint32_t a;
    asm("{ .reg .u64 t; cvta.to.shared.u64 t, %1; cvt.u32.u64 %0, t; }"
        : "=r"(a) : "l"(p));
    return a;
}
__device__ __forceinline__ void ldsm4(uint32_t (&r)[4], uint32_t addr) {
    asm volatile("ldmatrix.sync.aligned.m8n8.x4.shared.b16 {%0,%1,%2,%3}, [%4];"
                 : "=r"(r[0]), "=r"(r[1]), "=r"(r[2]), "=r"(r[3]) : "r"(addr));
}
__device__ __forceinline__ void mma16816(float (&d)[4], const uint32_t (&a)[4],
                                         uint32_t b0, uint32_t b1) {
    asm volatile("mma.sync.aligned.m16n8k16.row.col.f32.bf16.bf16.f32 "
                 "{%0,%1,%2,%3}, {%4,%5,%6,%7}, {%8,%9}, {%0,%1,%2,%3};"
                 : "+f"(d[0]), "+f"(d[1]), "+f"(d[2]), "+f"(d[3])
                 : "r"(a[0]), "r"(a[1]), "r"(a[2]), "r"(a[3]), "r"(b0), "r"(b1));
}
__device__ __forceinline__ void split2(float x, float y,
                                       __nv_bfloat162& h, __nv_bfloat162& l) {
    h.x = __float2bfloat16(x); h.y = __float2bfloat16(y);
    l.x = __float2bfloat16(x - __bfloat162float(h.x));
    l.y = __float2bfloat16(y - __bfloat162float(h.y));
}

// ===================== prep kernels =========================================
__global__ void __launch_bounds__(1024) split_x_kernel(const float* __restrict__ x) {
    size_t idx = (size_t)blockIdx.x * 1024 + threadIdx.x;  // float4 index
    float4 v = ((const float4*)x)[idx];
    __nv_bfloat162 h0, h1, l0, l1;
    split2(v.x, v.y, h0, l0);
    split2(v.z, v.w, h1, l1);
    ((__nv_bfloat162*)g_xhi)[idx * 2]     = h0;
    ((__nv_bfloat162*)g_xhi)[idx * 2 + 1] = h1;
    ((__nv_bfloat162*)g_xlo)[idx * 2]     = l0;
    ((__nv_bfloat162*)g_xlo)[idx * 2 + 1] = l1;
}

__global__ void __launch_bounds__(512) split_w_kernel(const float* __restrict__ qkv_w,
                                                      const float* __restrict__ proj_w) {
    int idx = blockIdx.x * 512 + threadIdx.x;
    float v; __nv_bfloat16 *ph, *pl; int off;
    if (idx < 196608) {
        int n = idx >> 8, k = idx & 255;
        v = qkv_w[k * 768 + n];
        ph = g_wqkv_hi; pl = g_wqkv_lo; off = n * 256 + k;
    } else {
        int j = idx - 196608;
        int n = j >> 8, k = j & 255;
        v = proj_w[k * 256 + n];
        ph = g_wproj_hi; pl = g_wproj_lo; off = n * 256 + k;
    }
    __nv_bfloat16 h = __float2bfloat16(v);
    ph[off] = h;
    pl[off] = __float2bfloat16(v - __bfloat162float(h));
}

// ===================== split-bf16 HMMA GEMM =================================
// C[128 x 128] tile = A[128 x 256] @ W^T, 3-term bf16 split, fp32 accum.
// MODE 0: A=X hi/lo, W=qkv_w; epilogue routes by n0 into Q/K (split bf16) or
//         V^T (split bf16, transposed per-window). MODE 1: A=O, W=proj, C=out.
#define T_AH 0
#define T_AL 10240
#define T_BH 20480
#define T_BL 30720

template<int MODE>
__global__ void __launch_bounds__(256, 2)
gemm_mma_kernel(const float* __restrict__ bias, float* __restrict__ Cext)
{
    __shared__ __align__(16) unsigned char sm[40960];
    const __nv_bfloat16* Ahi = (MODE == 0) ? g_xhi : g_ohi;
    const __nv_bfloat16* Alo = (MODE == 0) ? g_xlo : g_olo;
    const __nv_bfloat16* Whi = (MODE == 0) ? g_wqkv_hi : g_wproj_hi;
    const __nv_bfloat16* Wlo = (MODE == 0) ? g_wqkv_lo : g_wproj_lo;

    const int tid  = threadIdx.x;
    const int lane = tid & 31;
    const int wid  = tid >> 5;
    const int m0   = blockIdx.y * 128;     // m slow: consecutive CTAs share A via L2
    const int n0   = blockIdx.x * 128;
    const int wm   = (wid & 3) * 32;
    const int wn   = (wid >> 2) * 64;
    const uint32_t sb = smem_to_u32(sm);

    float acc[2][8][4];
#pragma unroll
    for (int a = 0; a < 2; ++a)
#pragma unroll
        for (int b = 0; b < 8; ++b)
#pragma unroll
            for (int c = 0; c < 4; ++c) acc[a][b][c] = 0.0f;

    const int arow = (lane & 7) + ((lane >> 3) & 1) * 8;
    const int kqof = (lane >> 4) * 8;

    for (int kc = 0; kc < 8; ++kc) {
        const int kb = kc * 32;
#pragma unroll
        for (int it = 0; it < 2; ++it) {
            int e   = tid + it * 256;      // 0..511 int4 slots
            int row = e >> 2;
            int kq  = e & 3;
            size_t goffA = (size_t)(m0 + row) * 256 + kb + kq * 8;
            size_t goffB = (size_t)(n0 + row) * 256 + kb + kq * 8;
            uint32_t soff = (uint32_t)(row * 80 + kq * 16);
            *(int4*)(sm + T_AH + soff) = *(const int4*)(Ahi + goffA);
            *(int4*)(sm + T_AL + soff) = *(const int4*)(Alo + goffA);
            *(int4*)(sm + T_BH + soff) = *(const int4*)(Whi + goffB);
            *(int4*)(sm + T_BL + soff) = *(const int4*)(Wlo + goffB);
        }
        __syncthreads();
#pragma unroll
        for (int ks = 0; ks < 2; ++ks) {
            const int kcol = ks * 16 + kqof;
            uint32_t ah[2][4], al[2][4];
#pragma unroll
            for (int mf = 0; mf < 2; ++mf) {
                uint32_t ad = sb + (uint32_t)((wm + mf * 16 + arow) * 80 + kcol * 2);
                ldsm4(ah[mf], ad + T_AH);
                ldsm4(al[mf], ad + T_AL);
            }
#pragma unroll
            for (int np = 0; np < 4; ++np) {
                uint32_t bd = sb + (uint32_t)((wn + np * 16 + arow) * 80 + kcol * 2);
                uint32_t bh[4], bl[4];
                ldsm4(bh, bd + T_BH);
                ldsm4(bl, bd + T_BL);
#pragma unroll
                for (int mf = 0; mf < 2; ++mf)
#pragma unroll
                    for (int nf = 0; nf < 2; ++nf) {
                        float (&d)[4] = acc[mf][np * 2 + nf];
                        mma16816(d, ah[mf], bh[nf], bh[nf + 2]);
                        mma16816(d, ah[mf], bl[nf], bl[nf + 2]);
                        mma16816(d, al[mf], bh[nf], bh[nf + 2]);
                    }
            }
        }
        __syncthreads();
    }

    // epilogue
    const int g   = lane >> 2;
    const int tg2 = (lane & 3) * 2;
#pragma unroll
    for (int mf = 0; mf < 2; ++mf) {
        const int row = m0 + wm + mf * 16 + g;      // rows row, row+8
#pragma unroll
        for (int nfi = 0; nfi < 8; ++nfi) {
            const int col = n0 + wn + nfi * 8 + tg2;
            float bx = __ldg(&bias[col]);
            float by = __ldg(&bias[col + 1]);
            float v0 = acc[mf][nfi][0] + bx, v1 = acc[mf][nfi][1] + by;  // row
            float v2 = acc[mf][nfi][2] + bx, v3 = acc[mf][nfi][3] + by;  // row+8
            if (MODE == 1) {
                *(float2*)&Cext[(size_t)row * 256 + col]       = make_float2(v0, v1);
                *(float2*)&Cext[(size_t)(row + 8) * 256 + col] = make_float2(v2, v3);
            } else if (n0 < 256) {                  // Q: scale 1/16, split
                v0 *= 0.0625f; v1 *= 0.0625f; v2 *= 0.0625f; v3 *= 0.0625f;
                __nv_bfloat162 h, l;
                split2(v0, v1, h, l);
                *(__nv_bfloat162*)&g_qh[(size_t)row * 256 + col] = h;
                *(__nv_bfloat162*)&g_ql[(size_t)row * 256 + col] = l;
                split2(v2, v3, h, l);
                *(__nv_bfloat162*)&g_qh[(size_t)(row + 8) * 256 + col] = h;
                *(__nv_bfloat162*)&g_ql[(size_t)(row + 8) * 256 + col] = l;
            } else if (n0 < 512) {                  // K: split
                int c = col - 256;
                __nv_bfloat162 h, l;
                split2(v0, v1, h, l);
                *(__nv_bfloat162*)&g_kh[(size_t)row * 256 + c] = h;
                *(__nv_bfloat162*)&g_kl[(size_t)row * 256 + c] = l;
                split2(v2, v3, h, l);
                *(__nv_bfloat162*)&g_kh[(size_t)(row + 8) * 256 + c] = h;
                *(__nv_bfloat162*)&g_kl[(size_t)(row + 8) * 256 + c] = l;
            } else {                                // V: split + transpose per window
                int d = col - 512;
#pragma unroll
                for (int rr = 0; rr < 2; ++rr) {
                    int r  = row + rr * 8;
                    float a0 = rr ? v2 : v0, a1 = rr ? v3 : v1;
                    size_t base = ((size_t)(r >> 6) * 256) * 64 + (r & 63);
                    __nv_bfloat16 h0 = __float2bfloat16(a0);
                    __nv_bfloat16 h1 = __float2bfloat16(a1);
                    g_vth[base + (size_t)d * 64]       = h0;
                    g_vth[base + (size_t)(d + 1) * 64] = h1;
                    g_vtl[base + (size_t)d * 64] =
                        __float2bfloat16(a0 - __bfloat162float(h0));
                    g_vtl[base + (size_t)(d + 1) * 64] =
                        __float2bfloat16(a1 - __bfloat162float(h1));
                }
            }
        }
    }
}

// ===================== attention (mma.sync, 256 threads) =====================
// smem bytes: Qh/Ql, Kh/Kl: 64 rows x 528B; Vt h/l: 256 rows x 144B;
// P h/l: 64 rows x 144B; reductions + bias tables.
#define AQ_H   0
#define AQ_L   33792
#define AK_H   67584
#define AK_L   101376
#define AVT_H  135168
#define AVT_L  172032
#define AP_H   208896
#define AP_L   218112
#define A_RED  227328      // pmax[128] floats, psum[128] floats
#define A_TAB  228352      // phi[0..14] @ +0, th[0..14] @ +16 floats
#define ATTN_SMEM 228480

__global__ void __launch_bounds__(256, 1)
attn_kernel(const float* __restrict__ theta_max,
            const float* __restrict__ a_p, const float* __restrict__ b_p,
            const float* __restrict__ a_r, const float* __restrict__ b_r)
{
    extern __shared__ unsigned char sm[];
    const uint32_t sb = smem_to_u32(sm);
    float* pmax = (float*)(sm + A_RED);
    float* psum = pmax + 128;
    float* tabf = (float*)(sm + A_TAB);

    const int tid  = threadIdx.x;
    const int lane = tid & 31;
    const int wid  = tid >> 5;
    const int w    = blockIdx.x;

    // bias tables: phi[dx+7], th[dy+7]
    if (tid < 15) {
        int dx = tid - 7;
        int ai = dx < 0 ? dx + 15 : dx;
        float s, c;
        sincosf((float)dx * (6.283185307179586f / 64.0f), &s, &c);
        tabf[tid] = __ldg(&a_p[ai]) * c + __ldg(&b_p[ai]) * s;
    } else if (tid >= 16 && tid < 31) {
        int dy = tid - 16 - 7;
        int ri = dy < 0 ? dy + 15 : dy;
        float tm = __ldg(&theta_max[w >> 6]);
        float s, c;
        sincosf((float)dy * (tm * 0.015625f), &s, &c);
        tabf[tid] = __ldg(&a_r[ri]) * c + __ldg(&b_r[ri]) * s;
    }

    // load Q,K (row-major [64][256]) and Vt ([256][64]) hi/lo into smem
    {
        const int4* qh = (const int4*)(g_qh + (size_t)w * 64 * 256);
        const int4* ql = (const int4*)(g_ql + (size_t)w * 64 * 256);
        const int4* kh = (const int4*)(g_kh + (size_t)w * 64 * 256);
        const int4* kl = (const int4*)(g_kl + (size_t)w * 64 * 256);
        const int4* vh = (const int4*)(g_vth + (size_t)w * 256 * 64);
        const int4* vl = (const int4*)(g_vtl + (size_t)w * 256 * 64);
#pragma unroll
        for (int it = 0; it < 8; ++it) {
            int e = tid + it * 256;            // 0..2047
            uint32_t so = (uint32_t)((e >> 5) * 528 + (e & 31) * 16);
            *(int4*)(sm + AQ_H + so) = qh[e];
            *(int4*)(sm + AQ_L + so) = ql[e];
            *(int4*)(sm + AK_H + so) = kh[e];
            *(int4*)(sm + AK_L + so) = kl[e];
            uint32_t sv = (uint32_t)((e >> 3) * 144 + (e & 7) * 16);
            *(int4*)(sm + AVT_H + sv) = vh[e];
            *(int4*)(sm + AVT_L + sv) = vl[e];
        }
    }
    __syncthreads();

    const int wm   = (wid & 3) * 16;
    const int wn2  = wid >> 2;                 // 0/1
    const int wn   = wn2 * 32;
    const int arow = (lane & 7) + ((lane >> 3) & 1) * 8;
    const int kqof = (lane >> 4) * 8;
    const int g    = lane >> 2;
    const int tg2  = (lane & 3) * 2;

    // ---- S = Q @ K^T (3-term split) ----
    float accS[4][4];
#pragma unroll
    for (int f = 0; f < 4; ++f)
#pragma unroll
        for (int c = 0; c < 4; ++c) accS[f][c] = 0.0f;

#pragma unroll
    for (int kk = 0; kk < 16; ++kk) {
        const int kcol = kk * 16 + kqof;
        uint32_t aoff = (uint32_t)((wm + arow) * 528 + kcol * 2);
        uint32_t ah[4], al[4];
        ldsm4(ah, sb + AQ_H + aoff);
        ldsm4(al, sb + AQ_L + aoff);
#pragma unroll
        for (int np = 0; np < 2; ++np) {
            uint32_t boff = (uint32_t)((wn + np * 16 + arow) * 528 + kcol * 2);
            uint32_t bh[4], bl[4];
            ldsm4(bh, sb + AK_H + boff);
            ldsm4(bl, sb + AK_L + boff);
#pragma unroll
            for (int nf = 0; nf < 2; ++nf) {
                float (&d)[4] = accS[np * 2 + nf];
                mma16816(d, ah, bh[nf], bh[nf + 2]);
                mma16816(d, ah, bl[nf], bl[nf + 2]);
                mma16816(d, al, bh[nf], bh[nf + 2]);
            }
        }
    }

    // ---- bias + softmax ----
    const int i0 = wm + g, i1 = i0 + 8;
    float m0v = -1e30f, m1v = -1e30f;
#pragma unroll
    for (int f = 0; f < 4; ++f) {
        int jb = wn + (f >> 1) * 16 + (f & 1) * 8 + tg2;
#pragma unroll
        for (int e = 0; e < 2; ++e) {
            int j   = jb + e;
            int dxi = (i0 & 7) - (j & 7) + 7;
            int dyi = (i0 >> 3) - (j >> 3) + 7;
            float phi = tabf[dxi];
            accS[f][e]     += phi + tabf[16 + dyi];
            accS[f][2 + e] += phi + tabf[16 + dyi + 1];
            m0v = fmaxf(m0v, accS[f][e]);
            m1v = fmaxf(m1v, accS[f][2 + e]);
        }
    }
    m0v = fmaxf(m0v, __shfl_xor_sync(0xffffffffu, m0v, 1));
    m0v = fmaxf(m0v, __shfl_xor_sync(0xffffffffu, m0v, 2));
    m1v = fmaxf(m1v, __shfl_xor_sync(0xffffffffu, m1v, 1));
    m1v = fmaxf(m1v, __shfl_xor_sync(0xffffffffu, m1v, 2));
    pmax[wn2 * 64 + i0] = m0v;
    pmax[wn2 * 64 + i1] = m1v;
    __syncthreads();
    const float mx0 = fmaxf(pmax[i0], pmax[64 + i0]);
    const float mx1 = fmaxf(pmax[i1], pmax[64 + i1]);

    float s0 = 0.0f, s1 = 0.0f;
#pragma unroll
    for (int f = 0; f < 4; ++f)
#pragma unroll
        for (int e = 0; e < 2; ++e) {
            accS[f][e]     = __expf(accS[f][e]     - mx0);
            accS[f][2 + e] = __expf(accS[f][2 + e] - mx1);
            s0 += accS[f][e];
            s1 += accS[f][2 + e];
        }
    s0 += __shfl_xor_sync(0xffffffffu, s0, 1);
    s0 += __shfl_xor_sync(0xffffffffu, s0, 2);
    s1 += __shfl_xor_sync(0xffffffffu, s1, 1);
    s1 += __shfl_xor_sync(0xffffffffu, s1, 2);
    psum[wn2 * 64 + i0] = s0;
    psum[wn2 * 64 + i1] = s1;
    __syncthreads();
    const float inv0 = 1.0f / (psum[i0] + psum[64 + i0]);
    const float inv1 = 1.0f / (psum[i1] + psum[64 + i1]);

    // store P hi/lo (bf16) to smem
#pragma unroll
    for (int f = 0; f < 4; ++f) {
        int jb = wn + (f >> 1) * 16 + (f & 1) * 8 + tg2;
        __nv_bfloat162 h, l;
        split2(accS[f][0] * inv0, accS[f][1] * inv0, h, l);
        *(__nv_bfloat162*)(sm + AP_H + i0 * 144 + jb * 2) = h;
        *(__nv_bfloat162*)(sm + AP_L + i0 * 144 + jb * 2) = l;
        split2(accS[f][2] * inv1, accS[f][3] * inv1, h, l);
        *(__nv_bfloat162*)(sm + AP_H + i1 * 144 + jb * 2) = h;
        *(__nv_bfloat162*)(sm + AP_L + i1 * 144 + jb * 2) = l;
    }
    __syncthreads();

    // ---- O = P @ V (B = V^T rows are d) ----
    float accO[16][4];
#pragma unroll
    for (int f = 0; f < 16; ++f)
#pragma unroll
        for (int c = 0; c < 4; ++c) accO[f][c] = 0.0f;

#pragma unroll
    for (int kk = 0; kk < 4; ++kk) {
        const int kcol = kk * 16 + kqof;
        uint32_t aoff = (uint32_t)((wm + arow) * 144 + kcol * 2);
        uint32_t ah[4], al[4];
        ldsm4(ah, sb + AP_H + aoff);
        ldsm4(al, sb + AP_L + aoff);
#pragma unroll
        for (int np = 0; np < 8; ++np) {
            uint32_t boff = (uint32_t)((wn2 * 128 + np * 16 + arow) * 144 + kcol * 2);
            uint32_t bh[4], bl[4];
            ldsm4(bh, sb + AVT_H + boff);
            ldsm4(bl, sb + AVT_L + boff);
#pragma unroll
            for (int nf = 0; nf < 2; ++nf) {
                float (&d)[4] = accO[np * 2 + nf];
                mma16816(d, ah, bh[nf], bh[nf + 2]);
                mma16816(d, ah, bl[nf], bl[nf + 2]);
                mma16816(d, al, bh[nf], bh[nf + 2]);
            }
        }
    }

    // epilogue: split O -> g_ohi/g_olo [row][256]
    const size_t r0 = (size_t)w * 64 + i0;
    const size_t r1 = (size_t)w * 64 + i1;
#pragma unroll
    for (int f = 0; f < 16; ++f) {
        int d = wn2 * 128 + (f >> 1) * 16 + (f & 1) * 8 + tg2;
        __nv_bfloat162 h, l;
        split2(accO[f][0], accO[f][1], h, l);
        *(__nv_bfloat162*)&g_ohi[r0 * 256 + d] = h;
        *(__nv_bfloat162*)&g_olo[r0 * 256 + d] = l;
        split2(accO[f][2], accO[f][3], h, l);
        *(__nv_bfloat162*)&g_ohi[r1 * 256 + d] = h;
        *(__nv_bfloat162*)&g_olo[r1 * 256 + d] = l;
    }
}

// ===================== launch ================================================
extern "C" void kernel_launch(void* const* d_in, const int* in_sizes, int n_in,
                              void* d_out, int out_size)
{
    (void)in_sizes; (void)n_in; (void)out_size;
    const float* x         = (const float*)d_in[0];
    const float* theta_max = (const float*)d_in[1];
    const float* qkv_w     = (const float*)d_in[2];
    const float* qkv_b     = (const float*)d_in[3];
    const float* proj_w    = (const float*)d_in[4];
    const float* proj_b    = (const float*)d_in[5];
    const float* a_p       = (const float*)d_in[6];
    const float* b_p       = (const float*)d_in[7];
    const float* a_r       = (const float*)d_in[8];
    const float* b_r       = (const float*)d_in[9];
    float* out = (float*)d_out;

    cudaFuncSetAttribute(attn_kernel,
                         cudaFuncAttributeMaxDynamicSharedMemorySize, ATTN_SMEM);

    split_x_kernel<<<16384, 1024>>>(x);
    split_w_kernel<<<512, 512>>>(qkv_w, proj_w);
    gemm_mma_kernel<0><<<dim3(6, 2048), 256>>>(qkv_b, nullptr);
    attn_kernel<<<4096, 256, ATTN_SMEM>>>(theta_max, a_p, b_p, a_r, b_r);
    gemm_mma_kernel<1><<<dim3(2, 2048), 256>>>(proj_b, out);
}

// round 10
// speedup vs baseline: 2.2554x; 1.0866x over previous
#include <cuda_runtime.h>
#include <cuda_bf16.h>
#include <cstdint>

// ===================== scratch (static device arrays; no allocs) ============
__device__ __nv_bfloat16  g_xhi[262144ull * 256];          // X split hi/lo
__device__ __nv_bfloat16  g_xlo[262144ull * 256];
__device__ __nv_bfloat16  g_qh[262144ull * 256];           // Q (scaled+bias) hi/lo
__device__ __nv_bfloat16  g_ql[262144ull * 256];
__device__ __nv_bfloat16  g_kh[262144ull * 256];           // K hi/lo
__device__ __nv_bfloat16  g_kl[262144ull * 256];
__device__ __nv_bfloat16  g_vth[4096ull * 256 * 64];       // V^T per window [d][j]
__device__ __nv_bfloat16  g_vtl[4096ull * 256 * 64];
__device__ __nv_bfloat16  g_ohi[262144ull * 256];          // attn out hi/lo
__device__ __nv_bfloat16  g_olo[262144ull * 256];
__device__ __nv_bfloat16  g_wqkv_hi[768 * 256];            // W^T [n][k]
__device__ __nv_bfloat16  g_wqkv_lo[768 * 256];
__device__ __nv_bfloat16  g_wproj_hi[256 * 256];
__device__ __nv_bfloat16  g_wproj_lo[256 * 256];

// ===================== helpers ==============================================
__device__ __forceinline__ uint32_t smem_to_u32(const void* p) {
    uint32_t a;
    asm("{ .reg .u64 t; cvta.to.shared.u64 t, %1; cvt.u32.u64 %0, t; }"
        : "=r"(a) : "l"(p));
    return a;
}
__device__ __forceinline__ void ldsm4(uint32_t (&r)[4], uint32_t addr) {
    asm volatile("ldmatrix.sync.aligned.m8n8.x4.shared.b16 {%0,%1,%2,%3}, [%4];"
                 : "=r"(r[0]), "=r"(r[1]), "=r"(r[2]), "=r"(r[3]) : "r"(addr));
}
__device__ __forceinline__ void mma16816(float (&d)[4], const uint32_t (&a)[4],
                                         uint32_t b0, uint32_t b1) {
    asm volatile("mma.sync.aligned.m16n8k16.row.col.f32.bf16.bf16.f32 "
                 "{%0,%1,%2,%3}, {%4,%5,%6,%7}, {%8,%9}, {%0,%1,%2,%3};"
                 : "+f"(d[0]), "+f"(d[1]), "+f"(d[2]), "+f"(d[3])
                 : "r"(a[0]), "r"(a[1]), "r"(a[2]), "r"(a[3]), "r"(b0), "r"(b1));
}
__device__ __forceinline__ void split2(float x, float y,
                                       __nv_bfloat162& h, __nv_bfloat162& l) {
    h.x = __float2bfloat16(x); h.y = __float2bfloat16(y);
    l.x = __float2bfloat16(x - __bfloat162float(h.x));
    l.y = __float2bfloat16(y - __bfloat162float(h.y));
}
#define CP16(dst, src) \
    asm volatile("cp.async.cg.shared.global [%0], [%1], 16;" \
        :: "r"((uint32_t)(dst)), "l"(__cvta_generic_to_global((const void*)(src))) : "memory")
#define CP_COMMIT() asm volatile("cp.async.commit_group;" ::: "memory")
#define CP_WAIT(n)  asm volatile("cp.async.wait_group %0;" :: "n"(n) : "memory")

// ===================== prep kernels =========================================
__global__ void __launch_bounds__(1024) split_x_kernel(const float* __restrict__ x) {
    size_t idx = (size_t)blockIdx.x * 1024 + threadIdx.x;  // float4 index
    float4 v = ((const float4*)x)[idx];
    __nv_bfloat162 h0, h1, l0, l1;
    split2(v.x, v.y, h0, l0);
    split2(v.z, v.w, h1, l1);
    ((__nv_bfloat162*)g_xhi)[idx * 2]     = h0;
    ((__nv_bfloat162*)g_xhi)[idx * 2 + 1] = h1;
    ((__nv_bfloat162*)g_xlo)[idx * 2]     = l0;
    ((__nv_bfloat162*)g_xlo)[idx * 2 + 1] = l1;
}

__global__ void __launch_bounds__(512) split_w_kernel(const float* __restrict__ qkv_w,
                                                      const float* __restrict__ proj_w) {
    int idx = blockIdx.x * 512 + threadIdx.x;
    float v; __nv_bfloat16 *ph, *pl; int off;
    if (idx < 196608) {
        int n = idx >> 8, k = idx & 255;
        v = qkv_w[k * 768 + n];
        ph = g_wqkv_hi; pl = g_wqkv_lo; off = n * 256 + k;
    } else {
        int j = idx - 196608;
        int n = j >> 8, k = j & 255;
        v = proj_w[k * 256 + n];
        ph = g_wproj_hi; pl = g_wproj_lo; off = n * 256 + k;
    }
    __nv_bfloat16 h = __float2bfloat16(v);
    ph[off] = h;
    pl[off] = __float2bfloat16(v - __bfloat162float(h));
}

// ===================== split-bf16 HMMA GEMM (cp.async 2-stage) ===============
// C[128 x 128] tile = A[128 x 256] @ W^T, 3-term bf16 split, fp32 accum.
#define T_AH 0
#define T_AL 10240
#define T_BH 20480
#define T_BL 30720
#define STAGE_BYTES 40960
#define GEMM_SMEM (2 * STAGE_BYTES)

template<int MODE>
__global__ void __launch_bounds__(256, 2)
gemm_mma_kernel(const float* __restrict__ bias, float* __restrict__ Cext)
{
    extern __shared__ unsigned char smg[];
    const __nv_bfloat16* Ahi = (MODE == 0) ? g_xhi : g_ohi;
    const __nv_bfloat16* Alo = (MODE == 0) ? g_xlo : g_olo;
    const __nv_bfloat16* Whi = (MODE == 0) ? g_wqkv_hi : g_wproj_hi;
    const __nv_bfloat16* Wlo = (MODE == 0) ? g_wqkv_lo : g_wproj_lo;

    const int tid  = threadIdx.x;
    const int lane = tid & 31;
    const int wid  = tid >> 5;
    const int m0   = blockIdx.y * 128;     // m slow: consecutive CTAs share A via L2
    const int n0   = blockIdx.x * 128;
    const int wm   = (wid & 3) * 32;
    const int wn   = (wid >> 2) * 64;
    const uint32_t sb = smem_to_u32(smg);

    float acc[2][8][4];
#pragma unroll
    for (int a = 0; a < 2; ++a)
#pragma unroll
        for (int b = 0; b < 8; ++b)
#pragma unroll
            for (int c = 0; c < 4; ++c) acc[a][b][c] = 0.0f;

    const int arow = (lane & 7) + ((lane >> 3) & 1) * 8;
    const int kqof = (lane >> 4) * 8;

    auto load_stage = [&](int kc, int s) {
        const int kb = kc * 32;
        const uint32_t base = sb + s * STAGE_BYTES;
#pragma unroll
        for (int it = 0; it < 2; ++it) {
            int e   = tid + it * 256;      // 0..511 int4 slots
            int row = e >> 2;
            int kq  = e & 3;
            size_t goffA = (size_t)(m0 + row) * 256 + kb + kq * 8;
            size_t goffB = (size_t)(n0 + row) * 256 + kb + kq * 8;
            uint32_t soff = (uint32_t)(row * 80 + kq * 16);
            CP16(base + T_AH + soff, Ahi + goffA);
            CP16(base + T_AL + soff, Alo + goffA);
            CP16(base + T_BH + soff, Whi + goffB);
            CP16(base + T_BL + soff, Wlo + goffB);
        }
    };

    load_stage(0, 0);
    CP_COMMIT();

    for (int kc = 0; kc < 8; ++kc) {
        if (kc < 7) {
            load_stage(kc + 1, (kc + 1) & 1);
            CP_COMMIT();
            CP_WAIT(1);
        } else {
            CP_WAIT(0);
        }
        __syncthreads();
        const uint32_t base = sb + (kc & 1) * STAGE_BYTES;
#pragma unroll
        for (int ks = 0; ks < 2; ++ks) {
            const int kcol = ks * 16 + kqof;
            uint32_t ah[2][4], al[2][4];
#pragma unroll
            for (int mf = 0; mf < 2; ++mf) {
                uint32_t ad = base + (uint32_t)((wm + mf * 16 + arow) * 80 + kcol * 2);
                ldsm4(ah[mf], ad + T_AH);
                ldsm4(al[mf], ad + T_AL);
            }
#pragma unroll
            for (int np = 0; np < 4; ++np) {
                uint32_t bd = base + (uint32_t)((wn + np * 16 + arow) * 80 + kcol * 2);
                uint32_t bh[4], bl[4];
                ldsm4(bh, bd + T_BH);
                ldsm4(bl, bd + T_BL);
#pragma unroll
                for (int mf = 0; mf < 2; ++mf)
#pragma unroll
                    for (int nf = 0; nf < 2; ++nf) {
                        float (&d)[4] = acc[mf][np * 2 + nf];
                        mma16816(d, ah[mf], bh[nf], bh[nf + 2]);
                        mma16816(d, ah[mf], bl[nf], bl[nf + 2]);
                        mma16816(d, al[mf], bh[nf], bh[nf + 2]);
                    }
            }
        }
        __syncthreads();
    }

    // epilogue
    const int g   = lane >> 2;
    const int tg2 = (lane & 3) * 2;
#pragma unroll
    for (int mf = 0; mf < 2; ++mf) {
        const int row = m0 + wm + mf * 16 + g;      // rows row, row+8
#pragma unroll
        for (int nfi = 0; nfi < 8; ++nfi) {
            const int col = n0 + wn + nfi * 8 + tg2;
            float bx = __ldg(&bias[col]);
            float by = __ldg(&bias[col + 1]);
            float v0 = acc[mf][nfi][0] + bx, v1 = acc[mf][nfi][1] + by;  // row
            float v2 = acc[mf][nfi][2] + bx, v3 = acc[mf][nfi][3] + by;  // row+8
            if (MODE == 1) {
                *(float2*)&Cext[(size_t)row * 256 + col]       = make_float2(v0, v1);
                *(float2*)&Cext[(size_t)(row + 8) * 256 + col] = make_float2(v2, v3);
            } else if (n0 < 256) {                  // Q: scale 1/16, split
                v0 *= 0.0625f; v1 *= 0.0625f; v2 *= 0.0625f; v3 *= 0.0625f;
                __nv_bfloat162 h, l;
                split2(v0, v1, h, l);
                *(__nv_bfloat162*)&g_qh[(size_t)row * 256 + col] = h;
                *(__nv_bfloat162*)&g_ql[(size_t)row * 256 + col] = l;
                split2(v2, v3, h, l);
                *(__nv_bfloat162*)&g_qh[(size_t)(row + 8) * 256 + col] = h;
                *(__nv_bfloat162*)&g_ql[(size_t)(row + 8) * 256 + col] = l;
            } else if (n0 < 512) {                  // K: split
                int c = col - 256;
                __nv_bfloat162 h, l;
                split2(v0, v1, h, l);
                *(__nv_bfloat162*)&g_kh[(size_t)row * 256 + c] = h;
                *(__nv_bfloat162*)&g_kl[(size_t)row * 256 + c] = l;
                split2(v2, v3, h, l);
                *(__nv_bfloat162*)&g_kh[(size_t)(row + 8) * 256 + c] = h;
                *(__nv_bfloat162*)&g_kl[(size_t)(row + 8) * 256 + c] = l;
            } else {                                // V: split + transpose per window
                int d = col - 512;
#pragma unroll
                for (int rr = 0; rr < 2; ++rr) {
                    int r  = row + rr * 8;
                    float a0 = rr ? v2 : v0, a1 = rr ? v3 : v1;
                    size_t base2 = ((size_t)(r >> 6) * 256) * 64 + (r & 63);
                    __nv_bfloat16 h0 = __float2bfloat16(a0);
                    __nv_bfloat16 h1 = __float2bfloat16(a1);
                    g_vth[base2 + (size_t)d * 64]       = h0;
                    g_vth[base2 + (size_t)(d + 1) * 64] = h1;
                    g_vtl[base2 + (size_t)d * 64] =
                        __float2bfloat16(a0 - __bfloat162float(h0));
                    g_vtl[base2 + (size_t)(d + 1) * 64] =
                        __float2bfloat16(a1 - __bfloat162float(h1));
                }
            }
        }
    }
}

// ===================== attention (mma.sync, 512 threads) =====================
// smem bytes: Qh/Ql, Kh/Kl: 64 rows x 528B; Vt h/l: 256 rows x 144B;
// P h/l: 64 rows x 144B; reductions (4 segments) + bias tables.
#define AQ_H   0
#define AQ_L   33792
#define AK_H   67584
#define AK_L   101376
#define AVT_H  135168
#define AVT_L  172032
#define AP_H   208896
#define AP_L   218112
#define A_RED  227328      // pmax[4][64] floats, psum[4][64] floats
#define A_TAB  229376      // phi[0..14] @ +0, th[0..14] @ +16 floats
#define ATTN_SMEM 229504

__global__ void __launch_bounds__(512, 1)
attn_kernel(const float* __restrict__ theta_max,
            const float* __restrict__ a_p, const float* __restrict__ b_p,
            const float* __restrict__ a_r, const float* __restrict__ b_r)
{
    extern __shared__ unsigned char sm[];
    const uint32_t sb = smem_to_u32(sm);
    float* pmax = (float*)(sm + A_RED);        // [4][64]
    float* psum = pmax + 256;                  // [4][64]
    float* tabf = (float*)(sm + A_TAB);

    const int tid  = threadIdx.x;
    const int lane = tid & 31;
    const int wid  = tid >> 5;
    const int w    = blockIdx.x;

    // async tile loads: group0 = Q,K; group1 = Vt
    {
        const int4* qh = (const int4*)(g_qh + (size_t)w * 64 * 256);
        const int4* ql = (const int4*)(g_ql + (size_t)w * 64 * 256);
        const int4* kh = (const int4*)(g_kh + (size_t)w * 64 * 256);
        const int4* kl = (const int4*)(g_kl + (size_t)w * 64 * 256);
        const int4* vh = (const int4*)(g_vth + (size_t)w * 256 * 64);
        const int4* vl = (const int4*)(g_vtl + (size_t)w * 256 * 64);
#pragma unroll
        for (int it = 0; it < 4; ++it) {
            int e = tid + it * 512;            // 0..2047
            uint32_t so = (uint32_t)((e >> 5) * 528 + (e & 31) * 16);
            CP16(sb + AQ_H + so, qh + e);
            CP16(sb + AQ_L + so, ql + e);
            CP16(sb + AK_H + so, kh + e);
            CP16(sb + AK_L + so, kl + e);
        }
        CP_COMMIT();
#pragma unroll
        for (int it = 0; it < 4; ++it) {
            int e = tid + it * 512;
            uint32_t sv = (uint32_t)((e >> 3) * 144 + (e & 7) * 16);
            CP16(sb + AVT_H + sv, vh + e);
            CP16(sb + AVT_L + sv, vl + e);
        }
        CP_COMMIT();
    }

    // bias tables: phi[dx+7] @ tabf[0..14], th[dy+7] @ tabf[16..30]
    if (tid < 15) {
        int dx = tid - 7;
        int ai = dx < 0 ? dx + 15 : dx;
        float s, c;
        sincosf((float)dx * (6.283185307179586f / 64.0f), &s, &c);
        tabf[tid] = __ldg(&a_p[ai]) * c + __ldg(&b_p[ai]) * s;
    } else if (tid >= 16 && tid < 31) {
        int dy = tid - 16 - 7;
        int ri = dy < 0 ? dy + 15 : dy;
        float tm = __ldg(&theta_max[w >> 6]);
        float s, c;
        sincosf((float)dy * (tm * 0.015625f), &s, &c);
        tabf[tid] = __ldg(&a_r[ri]) * c + __ldg(&b_r[ri]) * s;
    }

    CP_WAIT(1);                                // Q,K in smem
    __syncthreads();

    const int wm   = (wid & 3) * 16;
    const int wn2  = wid >> 2;                 // 0..3
    const int arow = (lane & 7) + ((lane >> 3) & 1) * 8;
    const int kqof = (lane >> 4) * 8;
    const int g    = lane >> 2;
    const int tg2  = (lane & 3) * 2;

    // ---- S = Q @ K^T (3-term split), warp tile 16m x 16n ----
    float accS[2][4];
#pragma unroll
    for (int f = 0; f < 2; ++f)
#pragma unroll
        for (int c = 0; c < 4; ++c) accS[f][c] = 0.0f;

#pragma unroll
    for (int kk = 0; kk < 16; ++kk) {
        const int kcol = kk * 16 + kqof;
        uint32_t aoff = (uint32_t)((wm + arow) * 528 + kcol * 2);
        uint32_t ah[4], al[4];
        ldsm4(ah, sb + AQ_H + aoff);
        ldsm4(al, sb + AQ_L + aoff);
        uint32_t boff = (uint32_t)((wn2 * 16 + arow) * 528 + kcol * 2);
        uint32_t bh[4], bl[4];
        ldsm4(bh, sb + AK_H + boff);
        ldsm4(bl, sb + AK_L + boff);
#pragma unroll
        for (int nf = 0; nf < 2; ++nf) {
            float (&d)[4] = accS[nf];
            mma16816(d, ah, bh[nf], bh[nf + 2]);
            mma16816(d, ah, bl[nf], bl[nf + 2]);
            mma16816(d, al, bh[nf], bh[nf + 2]);
        }
    }

    // ---- bias + softmax (rows i0, i1; 16-wide segment per warp) ----
    const int i0 = wm + g, i1 = i0 + 8;
    float m0v = -1e30f, m1v = -1e30f;
#pragma unroll
    for (int f = 0; f < 2; ++f) {
        int jb = wn2 * 16 + f * 8 + tg2;
#pragma unroll
        for (int e = 0; e < 2; ++e) {
            int j   = jb + e;
            int dxi = (i0 & 7) - (j & 7) + 7;
            int dyi = (i0 >> 3) - (j >> 3) + 7;
            float phi = tabf[dxi];
            accS[f][e]     += phi + tabf[16 + dyi];
            accS[f][2 + e] += phi + tabf[16 + dyi + 1];
            m0v = fmaxf(m0v, accS[f][e]);
            m1v = fmaxf(m1v, accS[f][2 + e]);
        }
    }
    m0v = fmaxf(m0v, __shfl_xor_sync(0xffffffffu, m0v, 1));
    m0v = fmaxf(m0v, __shfl_xor_sync(0xffffffffu, m0v, 2));
    m1v = fmaxf(m1v, __shfl_xor_sync(0xffffffffu, m1v, 1));
    m1v = fmaxf(m1v, __shfl_xor_sync(0xffffffffu, m1v, 2));
    pmax[wn2 * 64 + i0] = m0v;
    pmax[wn2 * 64 + i1] = m1v;
    __syncthreads();
    const float mx0 = fmaxf(fmaxf(pmax[i0], pmax[64 + i0]),
                            fmaxf(pmax[128 + i0], pmax[192 + i0]));
    const float mx1 = fmaxf(fmaxf(pmax[i1], pmax[64 + i1]),
                            fmaxf(pmax[128 + i1], pmax[192 + i1]));

    float s0 = 0.0f, s1 = 0.0f;
#pragma unroll
    for (int f = 0; f < 2; ++f)
#pragma unroll
        for (int e = 0; e < 2; ++e) {
            accS[f][e]     = __expf(accS[f][e]     - mx0);
            accS[f][2 + e] = __expf(accS[f][2 + e] - mx1);
            s0 += accS[f][e];
            s1 += accS[f][2 + e];
        }
    s0 += __shfl_xor_sync(0xffffffffu, s0, 1);
    s0 += __shfl_xor_sync(0xffffffffu, s0, 2);
    s1 += __shfl_xor_sync(0xffffffffu, s1, 1);
    s1 += __shfl_xor_sync(0xffffffffu, s1, 2);
    psum[wn2 * 64 + i0] = s0;
    psum[wn2 * 64 + i1] = s1;
    __syncthreads();
    const float inv0 = 1.0f / (psum[i0] + psum[64 + i0] + psum[128 + i0] + psum[192 + i0]);
    const float inv1 = 1.0f / (psum[i1] + psum[64 + i1] + psum[128 + i1] + psum[192 + i1]);

    // store P hi/lo (bf16) to smem
#pragma unroll
    for (int f = 0; f < 2; ++f) {
        int jb = wn2 * 16 + f * 8 + tg2;
        __nv_bfloat162 h, l;
        split2(accS[f][0] * inv0, accS[f][1] * inv0, h, l);
        *(__nv_bfloat162*)(sm + AP_H + i0 * 144 + jb * 2) = h;
        *(__nv_bfloat162*)(sm + AP_L + i0 * 144 + jb * 2) = l;
        split2(accS[f][2] * inv1, accS[f][3] * inv1, h, l);
        *(__nv_bfloat162*)(sm + AP_H + i1 * 144 + jb * 2) = h;
        *(__nv_bfloat162*)(sm + AP_L + i1 * 144 + jb * 2) = l;
    }
    CP_WAIT(0);                                // Vt in smem
    __syncthreads();

    // ---- O = P @ V, warp tile 16m x 64d ----
    float accO[8][4];
#pragma unroll
    for (int f = 0; f < 8; ++f)
#pragma unroll
        for (int c = 0; c < 4; ++c) accO[f][c] = 0.0f;

#pragma unroll
    for (int kk = 0; kk < 4; ++kk) {
        const int kcol = kk * 16 + kqof;
        uint32_t aoff = (uint32_t)((wm + arow) * 144 + kcol * 2);
        uint32_t ah[4], al[4];
        ldsm4(ah, sb + AP_H + aoff);
        ldsm4(al, sb + AP_L + aoff);
#pragma unroll
        for (int np = 0; np < 4; ++np) {
            uint32_t boff = (uint32_t)((wn2 * 64 + np * 16 + arow) * 144 + kcol * 2);
            uint32_t bh[4], bl[4];
            ldsm4(bh, sb + AVT_H + boff);
            ldsm4(bl, sb + AVT_L + boff);
#pragma unroll
            for (int nf = 0; nf < 2; ++nf) {
                float (&d)[4] = accO[np * 2 + nf];
                mma16816(d, ah, bh[nf], bh[nf + 2]);
                mma16816(d, ah, bl[nf], bl[nf + 2]);
                mma16816(d, al, bh[nf], bh[nf + 2]);
            }
        }
    }

    // epilogue: split O -> g_ohi/g_olo [row][256]
    const size_t r0 = (size_t)w * 64 + i0;
    const size_t r1 = (size_t)w * 64 + i1;
#pragma unroll
    for (int f = 0; f < 8; ++f) {
        int d = wn2 * 64 + (f >> 1) * 16 + (f & 1) * 8 + tg2;
        __nv_bfloat162 h, l;
        split2(accO[f][0], accO[f][1], h, l);
        *(__nv_bfloat162*)&g_ohi[r0 * 256 + d] = h;
        *(__nv_bfloat162*)&g_olo[r0 * 256 + d] = l;
        split2(accO[f][2], accO[f][3], h, l);
        *(__nv_bfloat162*)&g_ohi[r1 * 256 + d] = h;
        *(__nv_bfloat162*)&g_olo[r1 * 256 + d] = l;
    }
}

// ===================== launch ================================================
extern "C" void kernel_launch(void* const* d_in, const int* in_sizes, int n_in,
                              void* d_out, int out_size)
{
    (void)in_sizes; (void)n_in; (void)out_size;
    const float* x         = (const float*)d_in[0];
    const float* theta_max = (const float*)d_in[1];
    const float* qkv_w     = (const float*)d_in[2];
    const float* qkv_b     = (const float*)d_in[3];
    const float* proj_w    = (const float*)d_in[4];
    const float* proj_b    = (const float*)d_in[5];
    const float* a_p       = (const float*)d_in[6];
    const float* b_p       = (const float*)d_in[7];
    const float* a_r       = (const float*)d_in[8];
    const float* b_r       = (const float*)d_in[9];
    float* out = (float*)d_out;

    cudaFuncSetAttribute(gemm_mma_kernel<0>,
                         cudaFuncAttributeMaxDynamicSharedMemorySize, GEMM_SMEM);
    cudaFuncSetAttribute(gemm_mma_kernel<1>,
                         cudaFuncAttributeMaxDynamicSharedMemorySize, GEMM_SMEM);
    cudaFuncSetAttribute(attn_kernel,
                         cudaFuncAttributeMaxDynamicSharedMemorySize, ATTN_SMEM);

    split_x_kernel<<<16384, 1024>>>(x);
    split_w_kernel<<<512, 512>>>(qkv_w, proj_w);
    gemm_mma_kernel<0><<<dim3(6, 2048), 256, GEMM_SMEM>>>(qkv_b, nullptr);
    attn_kernel<<<4096, 512, ATTN_SMEM>>>(theta_max, a_p, b_p, a_r, b_r);
    gemm_mma_kernel<1><<<dim3(2, 2048), 256, GEMM_SMEM>>>(proj_b, out);
}